// round 11
// baseline (speedup 1.0000x reference)
#include <cuda_runtime.h>

// ---------------------------------------------------------------------------
// RMSPELoss: per-row permutation-invariant RMSE between logits[:, :4] (DoA
// estimates, radians) and the angles of the 4 one-hot label positions.
//
//   inputs  : d_in[0] = logits  float32 [131072, 181]
//             d_in[1] = labels  int32   [131072, 181]  (exactly 4 ones/row)
//   output  : mean over rows of sqrt(min_perm total / 4)
//
// R9: issue-bound fix. Permutation min via shared 4x4 cost matrix:
//   lanes 0-15 compute cost[i][j] in parallel (16 sqwrap instead of 96),
//   lanes 0-23 gather their permutation's entries with 4 variable-lane
//   shuffles (per-lane constant source indices). Both rows' logits in one
//   LDG. Scan (ballot+ffs) and fused last-block reduction kept from R7.
// ---------------------------------------------------------------------------

#define FULLMASK 0xFFFFFFFFu

constexpr int   BATCH    = 131072;
constexpr int   NC       = 181;
constexpr int   NBLOCK   = 148 * 8;        // one resident wave on GB300
constexpr int   NTHREAD  = 256;
constexpr int   WARPS_PB = NTHREAD / 32;

constexpr float PI_F       = 3.14159265358979323846f;
constexpr float TWO_PI_F   = 6.283185307179586f;
constexpr float INV_2PI_F  = 0.15915494309189535f;   // 1/(2*pi)
constexpr float DEG2RAD_F  = 0.017453292519943295f;  // pi/180
// x = d - (p-90)*deg2rad + pi  ==  fma(p, -deg2rad, d + SHIFT_F)
constexpr float SHIFT_F    = 90.0f * DEG2RAD_F + PI_F;

// Per-lane shuffle sources for the 24 permutations. Cost matrix entry (i,j)
// lives on lane 4*i+j (lanes 0-15). For permutation (p0,p1,p2,p3), the
// packed bytes are (4*0+p0, 4*1+p1, 4*2+p2, 4*3+p3). Lanes 24-31 replicate
// lane 0 (their totals are masked to +inf).
__constant__ unsigned c_srcs[32] = {
    0x0F0A0500u, 0x0E0B0500u, 0x0F090600u, 0x0D0B0600u, 0x0E090700u, 0x0D0A0700u,
    0x0F0A0401u, 0x0E0B0401u, 0x0F080601u, 0x0C0B0601u, 0x0E080701u, 0x0C0A0701u,
    0x0F090402u, 0x0D0B0402u, 0x0F080502u, 0x0C0B0502u, 0x0D080702u, 0x0C090702u,
    0x0E090403u, 0x0D0A0403u, 0x0E080503u, 0x0C0A0503u, 0x0D080603u, 0x0C090603u,
    0x0F0A0500u, 0x0F0A0500u, 0x0F0A0500u, 0x0F0A0500u,
    0x0F0A0500u, 0x0F0A0500u, 0x0F0A0500u, 0x0F0A0500u
};

// Static scratch (no allocation allowed).
__device__ float    g_partials[NBLOCK];
__device__ unsigned g_count = 0;           // self-resets each launch

// Fold one 32-int label chunk's ballot into the packed index accumulator.
// (Order of the 4 packed positions is irrelevant: min over all permutations
// is invariant to relabeling the 4 angles.)
__device__ __forceinline__ void scan_chunk(unsigned& acc, int v, int base) {
    unsigned m = __ballot_sync(FULLMASK, v == 1);
    while (m) { acc = (acc << 8) | (unsigned)(base + __ffs(m) - 1); m &= m - 1; }
}

// acc: 4 one-positions packed as bytes. myl: lanes 0-7 hold logits[r..r+1,0..3];
// rowsel selects which 4 lanes. Returns sqrt(min-perm total / 4) on lane 0.
__device__ __forceinline__ float row_rmse_fast(unsigned acc, float myl,
                                               int lane, int rowsel)
{
    // ---- cost matrix: lane 4*i+j holds sqwrap(d_i, ang_j) (lanes 0-15) ----
    const int   i  = (lane >> 2) & 3;
    const int   j  = lane & 3;
    const float pj = (float)((acc >> (8 * j)) & 0xFF);
    const float di = __shfl_sync(FULLMASK, myl, (rowsel << 2) + i);
    float x = fmaf(pj, -DEG2RAD_F, di + SHIFT_F);       // d - ang + pi
    float q = floorf(x * INV_2PI_F);
    float w = fmaf(-q, TWO_PI_F, x) - PI_F;
    float c = w * w;

    // ---- lanes 0-23: gather this permutation's 4 entries ----
    const unsigned s = c_srcs[lane];
    float t =  __shfl_sync(FULLMASK, c,  s        & 0xFF);
    t      +=  __shfl_sync(FULLMASK, c, (s >>  8) & 0xFF);
    t      +=  __shfl_sync(FULLMASK, c, (s >> 16) & 0xFF);
    t      +=  __shfl_sync(FULLMASK, c, (s >> 24) & 0xFF);
    t = (lane < 24) ? t : 3.4e38f;

    #pragma unroll
    for (int off = 16; off; off >>= 1)
        t = fminf(t, __shfl_xor_sync(FULLMASK, t, off));

    return sqrtf(t * 0.25f);
}

__global__ __launch_bounds__(NTHREAD)
void rmspe_fused(const float* __restrict__ logits, const int* __restrict__ labels,
                 float* __restrict__ out, int out_size)
{
    __shared__ float s_ws[WARPS_PB];
    __shared__ float s_red[NTHREAD];
    __shared__ int   s_last;

    const int lane = threadIdx.x & 31;
    const int wib  = threadIdx.x >> 5;
    const int gw   = (blockIdx.x * NTHREAD + threadIdx.x) >> 5;
    const int nw   = (NBLOCK * NTHREAD) >> 5;

    float wsum = 0.0f;

    // Two adjacent rows per iteration: front-batch all loads for MLP.
    for (int r = 2 * gw; r < BATCH; r += 2 * nw) {
        const int* la = labels + (long)r * NC;
        const int* lb = la + NC;

        int a0 = __ldcs(la + lane);
        int a1 = __ldcs(la + 32  + lane);
        int a2 = __ldcs(la + 64  + lane);
        int a3 = __ldcs(la + 96  + lane);
        int a4 = __ldcs(la + 128 + lane);
        int a5 = (lane < 21) ? __ldcs(la + 160 + lane) : 0;
        int b0 = __ldcs(lb + lane);
        int b1 = __ldcs(lb + 32  + lane);
        int b2 = __ldcs(lb + 64  + lane);
        int b3 = __ldcs(lb + 96  + lane);
        int b4 = __ldcs(lb + 128 + lane);
        int b5 = (lane < 21) ? __ldcs(lb + 160 + lane) : 0;
        // lanes 0-3: logits[r,0..3]; lanes 4-7: logits[r+1,0..3]
        float myl = (lane < 8)
                  ? __ldcs(logits + (long)(r + (lane >> 2)) * NC + (lane & 3))
                  : 0.0f;

        unsigned accA = 0u, accB = 0u;
        scan_chunk(accA, a0,   0); scan_chunk(accA, a1,  32);
        scan_chunk(accA, a2,  64); scan_chunk(accA, a3,  96);
        scan_chunk(accA, a4, 128); scan_chunk(accA, a5, 160);
        scan_chunk(accB, b0,   0); scan_chunk(accB, b1,  32);
        scan_chunk(accB, b2,  64); scan_chunk(accB, b3,  96);
        scan_chunk(accB, b4, 128); scan_chunk(accB, b5, 160);

        const float ra = row_rmse_fast(accA, myl, lane, 0);
        const float rb = row_rmse_fast(accB, myl, lane, 1);
        if (lane == 0) wsum += ra + rb;
    }

    // ---- block reduce (deterministic fixed tree) ----
    if (lane == 0) s_ws[wib] = wsum;
    __syncthreads();
    if (threadIdx.x == 0) {
        float b = 0.0f;
        #pragma unroll
        for (int i = 0; i < WARPS_PB; i++) b += s_ws[i];
        g_partials[blockIdx.x] = b;
        __threadfence();
        unsigned old = atomicAdd(&g_count, 1u);
        s_last = (old == NBLOCK - 1) ? 1 : 0;
    }
    __syncthreads();

    // ---- last block finishes: deterministic fixed-order tree over partials ----
    if (s_last) {
        __threadfence();
        float t = 0.0f;
        for (int i = threadIdx.x; i < NBLOCK; i += NTHREAD)
            t += __ldcg(&g_partials[i]);
        s_red[threadIdx.x] = t;
        __syncthreads();
        #pragma unroll
        for (int o = NTHREAD / 2; o; o >>= 1) {
            if (threadIdx.x < o) s_red[threadIdx.x] += s_red[threadIdx.x + o];
            __syncthreads();
        }
        // zero any extra output elements (d_out is poisoned)
        for (int i = 1 + threadIdx.x; i < out_size; i += NTHREAD)
            out[i] = 0.0f;
        if (threadIdx.x == 0) {
            out[0]  = s_red[0] * (1.0f / (float)BATCH);
            g_count = 0;                    // reset for next graph replay
        }
    }
}

extern "C" void kernel_launch(void* const* d_in, const int* in_sizes, int n_in,
                              void* d_out, int out_size)
{
    const float* logits = (const float*)d_in[0];
    const int*   labels = (const int*)d_in[1];
    (void)in_sizes; (void)n_in;

    rmspe_fused<<<NBLOCK, NTHREAD>>>(logits, labels, (float*)d_out, out_size);
}

// round 12
// speedup vs baseline: 1.1557x; 1.1557x over previous
#include <cuda_runtime.h>

// ---------------------------------------------------------------------------
// RMSPELoss: per-row permutation-invariant RMSE between logits[:, :4] (DoA
// estimates, radians) and the angles of the 4 one-hot label positions.
//
//   inputs  : d_in[0] = logits  float32 [131072, 181]
//             d_in[1] = labels  int32   [131072, 181]  (exactly 4 ones/row)
//   output  : mean over rows of sqrt(min_perm total / 4)
//
// R11: issue-slot diet. Tile-of-128-rows per 128-thread block:
//   Phase A: flat int4 scan of the tile (exactly 5792 aligned int4), rare
//            one-events scattered to per-row smem byte slots (atomic rank).
//   Phase B: thread-per-row: 16-entry cost matrix in registers + 2+2
//            assignment DP (6 column subsets) == min over all 24 perms,
//            ~48 ALU ops, zero shuffles.
//   Fused deterministic last-block reduction (counter self-resets).
// ---------------------------------------------------------------------------

constexpr int   BATCH    = 131072;
constexpr int   NC       = 181;
constexpr int   TILE     = 128;                 // rows per block
constexpr int   NTHREAD  = 128;
constexpr int   NBLOCK   = BATCH / TILE;        // 1024
constexpr int   TILE_I4  = TILE * NC / 4;       // 5792 int4 per tile (exact)
constexpr int   FULL_J   = TILE_I4 / NTHREAD;   // 45 full sweeps
constexpr int   TAIL     = TILE_I4 - FULL_J * NTHREAD;  // 32

constexpr float PI_F      = 3.14159265358979323846f;
constexpr float TWO_PI_F  = 6.283185307179586f;
constexpr float INV_2PI_F = 0.15915494309189535f;    // 1/(2*pi)
constexpr float DEG2RAD_F = 0.017453292519943295f;   // pi/180
// d - (p-90)*deg2rad + pi == fma(p, -deg2rad, d + SHIFT)
constexpr float SHIFT_F   = 90.0f * DEG2RAD_F + PI_F;

// Static scratch (no allocation allowed).
__device__ float    g_partials[NBLOCK];
__device__ unsigned g_count = 0;                // self-resets each launch

// squared wrapped difference; bi = d_i + SHIFT already folded.
__device__ __forceinline__ float sqwrap2(float bi, float pj) {
    float x = fmaf(pj, -DEG2RAD_F, bi);
    float q = floorf(x * INV_2PI_F);
    float w = fmaf(-q, TWO_PI_F, x) - PI_F;
    return w * w;
}

__global__ __launch_bounds__(NTHREAD)
void rmspe_kernel(const float* __restrict__ logits, const int* __restrict__ labels,
                  float* __restrict__ out, int out_size)
{
    __shared__ int      s_cnt[TILE];
    __shared__ unsigned s_posw[TILE];
    __shared__ float    s_red[NTHREAD];
    __shared__ int      s_last;

    const int tid = threadIdx.x;
    const int r0  = blockIdx.x * TILE;

    s_cnt[tid]  = 0;
    __syncthreads();

    unsigned char* s_posb = (unsigned char*)s_posw;
    const int4* base = (const int4*)(labels + (long)r0 * NC);   // 16B aligned

    // ---- Phase A: flat vectorized scan, scatter one-positions ----
    auto emit = [&](int f) {                     // f = flat int index in tile
        unsigned rr = (unsigned)f / 181u;        // row within tile
        unsigned cc = (unsigned)f - rr * 181u;   // column (0..180)
        int rank = atomicAdd(&s_cnt[rr], 1);
        s_posb[rr * 4 + rank] = (unsigned char)cc;
    };

    #pragma unroll 1
    for (int j = 0; j < FULL_J; j += 5) {
        int4 v[5];
        #pragma unroll
        for (int u = 0; u < 5; u++)
            v[u] = __ldcs(base + tid + NTHREAD * (j + u));
        #pragma unroll
        for (int u = 0; u < 5; u++) {
            int4 w = v[u];
            if (w.x | w.y | w.z | w.w) {
                int f = (tid + NTHREAD * (j + u)) * 4;
                if (w.x) emit(f);
                if (w.y) emit(f + 1);
                if (w.z) emit(f + 2);
                if (w.w) emit(f + 3);
            }
        }
    }
    if (tid < TAIL) {
        int4 w = __ldcs(base + FULL_J * NTHREAD + tid);
        if (w.x | w.y | w.z | w.w) {
            int f = (FULL_J * NTHREAD + tid) * 4;
            if (w.x) emit(f);
            if (w.y) emit(f + 1);
            if (w.z) emit(f + 2);
            if (w.w) emit(f + 3);
        }
    }
    __syncthreads();

    // ---- Phase B: thread-per-row, cost matrix + 2+2 assignment DP ----
    const unsigned pw = s_posw[tid];
    const float* lg = logits + (long)(r0 + tid) * NC;
    const float b0 = __ldcs(lg)     + SHIFT_F;
    const float b1 = __ldcs(lg + 1) + SHIFT_F;
    const float b2 = __ldcs(lg + 2) + SHIFT_F;
    const float b3 = __ldcs(lg + 3) + SHIFT_F;

    float pj[4];
    pj[0] = (float)( pw        & 0xFFu);
    pj[1] = (float)((pw >>  8) & 0xFFu);
    pj[2] = (float)((pw >> 16) & 0xFFu);
    pj[3] = (float)((pw >> 24) & 0xFFu);

    float C[4][4];
    #pragma unroll
    for (int j = 0; j < 4; j++) {
        C[0][j] = sqwrap2(b0, pj[j]);
        C[1][j] = sqwrap2(b1, pj[j]);
        C[2][j] = sqwrap2(b2, pj[j]);
        C[3][j] = sqwrap2(b3, pj[j]);
    }

    // min over all 24 perms = min over 6 unordered column pairs for rows {0,1}
    float best = 3.4e38f;
    #pragma unroll
    for (int s = 0; s < 6; s++) {
        // subsets {a,b} for rows {0,1}; complement {c,d} for rows {2,3}
        const int a = (s < 3) ? 0 : (s < 5) ? 1 : 2;
        const int b = (s == 0) ? 1 : (s == 1 || s == 3) ? 2 : 3;
        const int c = (s == 5) ? 0 : (s >= 3) ? 0 : (s == 0) ? 2 : 1;
        const int d = (s == 0) ? 3 : (s == 1) ? 3 : (s == 2) ? 2 :
                      (s == 3) ? 3 : (s == 4) ? 2 : 1;
        float m01 = fminf(C[0][a] + C[1][b], C[0][b] + C[1][a]);
        float m23 = fminf(C[2][c] + C[3][d], C[2][d] + C[3][c]);
        best = fminf(best, m01 + m23);
    }

    const float rmse = sqrtf(best * 0.25f);

    // ---- block reduce (deterministic fixed tree) ----
    s_red[tid] = rmse;
    __syncthreads();
    #pragma unroll
    for (int o = NTHREAD / 2; o; o >>= 1) {
        if (tid < o) s_red[tid] += s_red[tid + o];
        __syncthreads();
    }
    if (tid == 0) {
        g_partials[blockIdx.x] = s_red[0];
        __threadfence();
        unsigned old = atomicAdd(&g_count, 1u);
        s_last = (old == NBLOCK - 1) ? 1 : 0;
    }
    __syncthreads();

    // ---- last block finishes: deterministic fixed-order tree over partials ----
    if (s_last) {
        __threadfence();
        float t = 0.0f;
        for (int i = tid; i < NBLOCK; i += NTHREAD)
            t += __ldcg(&g_partials[i]);
        s_red[tid] = t;
        __syncthreads();
        #pragma unroll
        for (int o = NTHREAD / 2; o; o >>= 1) {
            if (tid < o) s_red[tid] += s_red[tid + o];
            __syncthreads();
        }
        for (int i = 1 + tid; i < out_size; i += NTHREAD)
            out[i] = 0.0f;
        if (tid == 0) {
            out[0]  = s_red[0] * (1.0f / (float)BATCH);
            g_count = 0;                    // reset for next graph replay
        }
    }
}

extern "C" void kernel_launch(void* const* d_in, const int* in_sizes, int n_in,
                              void* d_out, int out_size)
{
    const float* logits = (const float*)d_in[0];
    const int*   labels = (const int*)d_in[1];
    (void)in_sizes; (void)n_in;

    rmspe_kernel<<<NBLOCK, NTHREAD>>>(logits, labels, (float*)d_out, out_size);
}

// round 13
// speedup vs baseline: 1.7992x; 1.5568x over previous
#include <cuda_runtime.h>

// ---------------------------------------------------------------------------
// RMSPELoss: per-row permutation-invariant RMSE between logits[:, :4] (DoA
// estimates, radians) and the angles of the 4 one-hot label positions.
//
//   inputs  : d_in[0] = logits  float32 [131072, 181]
//             d_in[1] = labels  int32   [131072, 181]  (exactly 4 ones/row)
//   output  : mean over rows of sqrt(min_perm total / 4)
//
// R12: occupancy fix. Same structure as R11 (flat int4 tile scan + smem
// scatter + thread-per-row 2+2 assignment DP + fused deterministic
// reduction), but 256 threads per 128-row tile: Phase A parallelism is
// decoupled from the row count, doubling resident warps (occ 39% -> ~86%)
// to cover DRAM latency. Phase B runs on the first 128 threads.
// ---------------------------------------------------------------------------

constexpr int   BATCH    = 131072;
constexpr int   NC       = 181;
constexpr int   TILE     = 128;                 // rows per block
constexpr int   NTHREAD  = 256;                 // 2x threads per tile
constexpr int   NBLOCK   = BATCH / TILE;        // 1024
constexpr int   TILE_I4  = TILE * NC / 4;       // 5792 int4 per tile (exact)
// 5792 = 256*22 + 160  ->  20 batched sweeps + 2 full + 1 guarded (tid<160)
constexpr int   TAIL     = TILE_I4 - 22 * NTHREAD;      // 160

constexpr float PI_F      = 3.14159265358979323846f;
constexpr float TWO_PI_F  = 6.283185307179586f;
constexpr float INV_2PI_F = 0.15915494309189535f;    // 1/(2*pi)
constexpr float DEG2RAD_F = 0.017453292519943295f;   // pi/180
// d - (p-90)*deg2rad + pi == fma(p, -deg2rad, d + SHIFT)
constexpr float SHIFT_F   = 90.0f * DEG2RAD_F + PI_F;

// Static scratch (no allocation allowed).
__device__ float    g_partials[NBLOCK];
__device__ unsigned g_count = 0;                // self-resets each launch

// squared wrapped difference; bi = d_i + SHIFT already folded.
__device__ __forceinline__ float sqwrap2(float bi, float pj) {
    float x = fmaf(pj, -DEG2RAD_F, bi);
    float q = floorf(x * INV_2PI_F);
    float w = fmaf(-q, TWO_PI_F, x) - PI_F;
    return w * w;
}

__global__ __launch_bounds__(NTHREAD)
void rmspe_kernel(const float* __restrict__ logits, const int* __restrict__ labels,
                  float* __restrict__ out, int out_size)
{
    __shared__ int      s_cnt[TILE];
    __shared__ unsigned s_posw[TILE];
    __shared__ float    s_red[NTHREAD];
    __shared__ int      s_last;

    const int tid = threadIdx.x;
    const int r0  = blockIdx.x * TILE;

    if (tid < TILE) s_cnt[tid] = 0;
    __syncthreads();

    unsigned char* s_posb = (unsigned char*)s_posw;
    const int4* base = (const int4*)(labels + (long)r0 * NC);   // 16B aligned

    // ---- Phase A: flat vectorized scan, scatter one-positions ----
    auto emit = [&](int f) {                     // f = flat int index in tile
        unsigned rr = (unsigned)f / 181u;        // row within tile
        unsigned cc = (unsigned)f - rr * 181u;   // column (0..180)
        int rank = atomicAdd(&s_cnt[rr], 1);
        s_posb[rr * 4 + rank] = (unsigned char)cc;
    };
    auto sift = [&](int4 w, int i4) {            // i4 = int4 index in tile
        if (w.x | w.y | w.z | w.w) {
            int f = i4 * 4;
            if (w.x) emit(f);
            if (w.y) emit(f + 1);
            if (w.z) emit(f + 2);
            if (w.w) emit(f + 3);
        }
    };

    #pragma unroll 1
    for (int j = 0; j < 20; j += 5) {
        int4 v[5];
        #pragma unroll
        for (int u = 0; u < 5; u++)
            v[u] = __ldcs(base + tid + NTHREAD * (j + u));
        #pragma unroll
        for (int u = 0; u < 5; u++)
            sift(v[u], tid + NTHREAD * (j + u));
    }
    {
        int4 v20 = __ldcs(base + tid + NTHREAD * 20);
        int4 v21 = __ldcs(base + tid + NTHREAD * 21);
        int4 v22 = make_int4(0, 0, 0, 0);
        if (tid < TAIL) v22 = __ldcs(base + tid + NTHREAD * 22);
        sift(v20, tid + NTHREAD * 20);
        sift(v21, tid + NTHREAD * 21);
        sift(v22, tid + NTHREAD * 22);
    }
    __syncthreads();

    // ---- Phase B: threads 0-127, one row each: cost matrix + 2+2 DP ----
    float rmse = 0.0f;
    if (tid < TILE) {
        const unsigned pw = s_posw[tid];
        const float* lg = logits + (long)(r0 + tid) * NC;
        const float b0 = __ldcs(lg)     + SHIFT_F;
        const float b1 = __ldcs(lg + 1) + SHIFT_F;
        const float b2 = __ldcs(lg + 2) + SHIFT_F;
        const float b3 = __ldcs(lg + 3) + SHIFT_F;

        float pj[4];
        pj[0] = (float)( pw        & 0xFFu);
        pj[1] = (float)((pw >>  8) & 0xFFu);
        pj[2] = (float)((pw >> 16) & 0xFFu);
        pj[3] = (float)((pw >> 24) & 0xFFu);

        float C[4][4];
        #pragma unroll
        for (int j = 0; j < 4; j++) {
            C[0][j] = sqwrap2(b0, pj[j]);
            C[1][j] = sqwrap2(b1, pj[j]);
            C[2][j] = sqwrap2(b2, pj[j]);
            C[3][j] = sqwrap2(b3, pj[j]);
        }

        // min over all 24 perms = min over 6 unordered column pairs for
        // rows {0,1} x 2 orderings x 2 orderings of the complement.
        float best = 3.4e38f;
        #pragma unroll
        for (int s = 0; s < 6; s++) {
            const int a = (s < 3) ? 0 : (s < 5) ? 1 : 2;
            const int b = (s == 0) ? 1 : (s == 1 || s == 3) ? 2 : 3;
            const int c = (s == 5) ? 0 : (s >= 3) ? 0 : (s == 0) ? 2 : 1;
            const int d = (s == 0) ? 3 : (s == 1) ? 3 : (s == 2) ? 2 :
                          (s == 3) ? 3 : (s == 4) ? 2 : 1;
            float m01 = fminf(C[0][a] + C[1][b], C[0][b] + C[1][a]);
            float m23 = fminf(C[2][c] + C[3][d], C[2][d] + C[3][c]);
            best = fminf(best, m01 + m23);
        }
        rmse = sqrtf(best * 0.25f);
    }

    // ---- block reduce (deterministic fixed tree over all 256 threads) ----
    s_red[tid] = rmse;
    __syncthreads();
    #pragma unroll
    for (int o = NTHREAD / 2; o; o >>= 1) {
        if (tid < o) s_red[tid] += s_red[tid + o];
        __syncthreads();
    }
    if (tid == 0) {
        g_partials[blockIdx.x] = s_red[0];
        __threadfence();
        unsigned old = atomicAdd(&g_count, 1u);
        s_last = (old == NBLOCK - 1) ? 1 : 0;
    }
    __syncthreads();

    // ---- last block finishes: deterministic fixed-order tree over partials ----
    if (s_last) {
        __threadfence();
        float t = 0.0f;
        for (int i = tid; i < NBLOCK; i += NTHREAD)
            t += __ldcg(&g_partials[i]);
        s_red[tid] = t;
        __syncthreads();
        #pragma unroll
        for (int o = NTHREAD / 2; o; o >>= 1) {
            if (tid < o) s_red[tid] += s_red[tid + o];
            __syncthreads();
        }
        for (int i = 1 + tid; i < out_size; i += NTHREAD)
            out[i] = 0.0f;
        if (tid == 0) {
            out[0]  = s_red[0] * (1.0f / (float)BATCH);
            g_count = 0;                    // reset for next graph replay
        }
    }
}

extern "C" void kernel_launch(void* const* d_in, const int* in_sizes, int n_in,
                              void* d_out, int out_size)
{
    const float* logits = (const float*)d_in[0];
    const int*   labels = (const int*)d_in[1];
    (void)in_sizes; (void)n_in;

    rmspe_kernel<<<NBLOCK, NTHREAD>>>(logits, labels, (float*)d_out, out_size);
}